// round 10
// baseline (speedup 1.0000x reference)
#include <cuda_runtime.h>
#include <cuda_fp16.h>
#include <cstdint>

#define dE 8
#define dH 1024
#define dI 4096
#define dN 2048
#define dK 2
#define dNK 4096

#define TBK 32
#define NTH 256

// smem: row stride 20 words (80B) — 16B-aligned rows for ldmatrix,
// (5r + kw/4) mod 8 hits all 8 bank quads per ldmatrix phase (conflict-free)
#define AST 20

// ---- GEMM1 geometry: CTA 256x64, warp tile 64x32 (dual-matrix) ----
#define G1_TBM 256
#define G1_TBN 64
#define G1_AW (G1_TBM * AST)          // 5120 words per stage
#define G1_BW (G1_TBN * AST)          // 1280 words per stage

// ---- GEMM2 geometry: CTA 128x128, warp tile 32x64 ----
#define G2_TBM 128
#define G2_TBN 128
#define G2_AW (G2_TBM * AST)          // 2560
#define G2_BW (G2_TBN * AST)          // 2560

// ---- scratch (device globals; no runtime allocation) ----
__device__ int    g_pairs[dNK];
__device__ int    g_off[dE + 1];
__device__ __half g_h[(size_t)dNK * dI];   // SwiGLU hidden, fp16 (32 MB)

__device__ __forceinline__ uint32_t su32(const void* p) {
    return (uint32_t)__cvta_generic_to_shared(p);
}
__device__ __forceinline__ uint32_t packh2(float lo, float hi) {
    __half2 h = __floats2half2_rn(lo, hi);
    return *(uint32_t*)&h;
}
__device__ __forceinline__ void mma_f16(float* d, const uint32_t* a, const uint32_t* b) {
    asm volatile("mma.sync.aligned.m16n8k16.row.col.f32.f16.f16.f32 "
                 "{%0,%1,%2,%3}, {%4,%5,%6,%7}, {%8,%9}, {%0,%1,%2,%3};\n"
                 : "+f"(d[0]), "+f"(d[1]), "+f"(d[2]), "+f"(d[3])
                 : "r"(a[0]), "r"(a[1]), "r"(a[2]), "r"(a[3]),
                   "r"(b[0]), "r"(b[1]));
}
__device__ __forceinline__ void ldmx4(uint32_t* r, uint32_t addr) {
    asm volatile("ldmatrix.sync.aligned.m8n8.x4.shared.b16 {%0,%1,%2,%3}, [%4];"
                 : "=r"(r[0]), "=r"(r[1]), "=r"(r[2]), "=r"(r[3]) : "r"(addr));
}

// ---- routing: histogram + scan + scatter, single CTA ----
__global__ void route_kernel(const int* __restrict__ idx) {
    __shared__ int s_cnt[dE], s_base[dE];
    int t = threadIdx.x;
    if (t < dE) s_cnt[t] = 0;
    __syncthreads();
    for (int p = t; p < dNK; p += blockDim.x) atomicAdd(&s_cnt[idx[p]], 1);
    __syncthreads();
    if (t == 0) {
        int acc = 0;
        for (int e = 0; e < dE; ++e) { g_off[e] = acc; s_base[e] = acc; acc += s_cnt[e]; }
        g_off[dE] = acc;
    }
    __syncthreads();
    if (t < dE) s_cnt[t] = 0;
    __syncthreads();
    for (int p = t; p < dNK; p += blockDim.x) {
        int e = idx[p];
        int slot = s_base[e] + atomicAdd(&s_cnt[e], 1);
        g_pairs[slot] = p;
    }
}

// ---- zero the output (gemm2 accumulates into it atomically) ----
__global__ void zero_out_kernel(float* __restrict__ out) {
    int i = blockIdx.x * blockDim.x + threadIdx.x;
    if (i < dN * dH / 4) ((float4*)out)[i] = make_float4(0.f, 0.f, 0.f, 0.f);
}

// ============ GEMM1: CTA 256x64, warp 64x32 dual — h = silu(x@w1)*(x@w3) ============
__global__ void __launch_bounds__(NTH, 1)
gemm1_mma(const float* __restrict__ x,
          const float* __restrict__ w1,
          const float* __restrict__ w3) {
    const int e    = blockIdx.z;
    const int mEnd = g_off[e + 1];
    const int m0   = g_off[e] + blockIdx.x * G1_TBM;
    if (m0 >= mEnd) return;
    const int i0 = blockIdx.y * G1_TBN;

    extern __shared__ uint32_t dsm[];   // 2*G1_AW + 4*G1_BW words = 60 KB
    __shared__ int s_tok[G1_TBM];

    const int t = threadIdx.x;
    const int w = t >> 5, l = t & 31;
    const int wm = w & 3, wn = w >> 2;      // warp tile 64x32: wm in 0..3, wn in 0..1
    const int lr = l >> 2, lc = l & 3;
    const uint32_t smb = su32(dsm);
    const int lmRow = l & 15;
    const int lmChk = (l >> 4) * 4;

    {
        int s = m0 + t;
        s_tok[t] = (s < mEnd && t < G1_TBM) ? g_pairs[s] / dK : -1;
    }
    __syncthreads();

    const float* w1e = w1 + (size_t)e * dH * dI + i0;
    const float* w3e = w3 + (size_t)e * dH * dI + i0;

    // A staging: 256 rows x 32k halfs -> 8 float4 per thread
    int aOffB[8], aOffW[8];
    #pragma unroll
    for (int p = 0; p < 8; ++p) {
        int id = t + p * NTH;
        int row = id >> 3, ch = id & 7;
        aOffW[p] = row * AST + ch * 2;
        int tok = s_tok[row];
        aOffB[p] = (tok < 0 ? 0 : tok) * (dH * 4) + ch * 16;
    }
    // B staging: n = t&63, kb = (t>>6)*8
    const int bN = t & 63, bKb = (t >> 6) * 8;
    const int bOffW = bN * AST + (bKb >> 1);
    const float* b1Src = w1e + (size_t)bKb * dI + bN;
    const float* b3Src = w3e + (size_t)bKb * dI + bN;

    uint32_t uA[8][2], uB1[4], uB3[4];

    auto ldg_stage = [&](int kt) {
        const int k0b = kt * TBK * 4;
        #pragma unroll
        for (int p = 0; p < 8; ++p) {
            float4 v = *(const float4*)((const char*)x + aOffB[p] + k0b);
            uA[p][0] = packh2(v.x, v.y);
            uA[p][1] = packh2(v.z, v.w);
        }
        const float* pb1 = b1Src + (size_t)(kt * TBK) * dI;
        const float* pb3 = b3Src + (size_t)(kt * TBK) * dI;
        #pragma unroll
        for (int jj = 0; jj < 4; ++jj) {
            uB1[jj] = packh2(pb1[(size_t)(2 * jj) * dI], pb1[(size_t)(2 * jj + 1) * dI]);
            uB3[jj] = packh2(pb3[(size_t)(2 * jj) * dI], pb3[(size_t)(2 * jj + 1) * dI]);
        }
    };
    auto sts_stage = [&](int s) {
        #pragma unroll
        for (int p = 0; p < 8; ++p)
            *(uint2*)&dsm[s * G1_AW + aOffW[p]] = make_uint2(uA[p][0], uA[p][1]);
        *(uint4*)&dsm[2 * G1_AW + s * G1_BW + bOffW] =
            make_uint4(uB1[0], uB1[1], uB1[2], uB1[3]);
        *(uint4*)&dsm[2 * G1_AW + 2 * G1_BW + s * G1_BW + bOffW] =
            make_uint4(uB3[0], uB3[1], uB3[2], uB3[3]);
    };

    float accG[4][4][4] = {};
    float accU[4][4][4] = {};

    const int KT = dH / TBK;   // 32
    ldg_stage(0);
    sts_stage(0);
    __syncthreads();

    for (int kt = 0; kt < KT; ++kt) {
        const int s = kt & 1;
        if (kt + 1 < KT) ldg_stage(kt + 1);

        #pragma unroll
        for (int ks = 0; ks < 2; ++ks) {
            const int kw = ks * 8 + lmChk;
            uint32_t af[4][4];
            #pragma unroll
            for (int mi = 0; mi < 4; ++mi) {
                int r = wm * 64 + mi * 16 + lmRow;
                ldmx4(af[mi], smb + 4u * (uint32_t)(s * G1_AW + r * AST + kw));
            }
            uint32_t b1f[4][2], b3f[4][2];
            #pragma unroll
            for (int np = 0; np < 2; ++np) {
                int n = wn * 32 + np * 16 + lmRow;
                uint32_t q[4];
                ldmx4(q, smb + 4u * (uint32_t)(2 * G1_AW + s * G1_BW + n * AST + kw));
                b1f[np * 2][0] = q[0]; b1f[np * 2 + 1][0] = q[1];
                b1f[np * 2][1] = q[2]; b1f[np * 2 + 1][1] = q[3];
                ldmx4(q, smb + 4u * (uint32_t)(2 * G1_AW + 2 * G1_BW + s * G1_BW + n * AST + kw));
                b3f[np * 2][0] = q[0]; b3f[np * 2 + 1][0] = q[1];
                b3f[np * 2][1] = q[2]; b3f[np * 2 + 1][1] = q[3];
            }
            #pragma unroll
            for (int ni = 0; ni < 4; ++ni)
                #pragma unroll
                for (int mi = 0; mi < 4; ++mi) {
                    mma_f16(accG[mi][ni], af[mi], b1f[ni]);
                    mma_f16(accU[mi][ni], af[mi], b3f[ni]);
                }
        }

        if (kt + 1 < KT) sts_stage(s ^ 1);
        __syncthreads();
    }

    #pragma unroll
    for (int mi = 0; mi < 4; ++mi) {
        int r0 = m0 + wm * 64 + mi * 16 + lr;
        int r1 = r0 + 8;
        #pragma unroll
        for (int ni = 0; ni < 4; ++ni) {
            int c = i0 + wn * 32 + ni * 8 + lc * 2;
            if (r0 < mEnd) {
                float g0 = accG[mi][ni][0], g1 = accG[mi][ni][1];
                float u0 = accU[mi][ni][0], u1 = accU[mi][ni][1];
                float h0 = g0 / (1.0f + __expf(-g0)) * u0;
                float h1 = g1 / (1.0f + __expf(-g1)) * u1;
                *(uint32_t*)&g_h[(size_t)r0 * dI + c] = packh2(h0, h1);
            }
            if (r1 < mEnd) {
                float g2 = accG[mi][ni][2], g3 = accG[mi][ni][3];
                float u2 = accU[mi][ni][2], u3 = accU[mi][ni][3];
                float h2 = g2 / (1.0f + __expf(-g2)) * u2;
                float h3 = g3 / (1.0f + __expf(-g3)) * u3;
                *(uint32_t*)&g_h[(size_t)r1 * dI + c] = packh2(h2, h3);
            }
        }
    }
}

// ============ GEMM2: CTA 128x128, warp 32x64 — out += ew * (h @ w2) ============
__global__ void __launch_bounds__(NTH, 2)
gemm2_mma(const float* __restrict__ ew,
          const float* __restrict__ w2,
          float* __restrict__ out) {
    const int e    = blockIdx.z;
    const int mEnd = g_off[e + 1];
    const int m0   = g_off[e] + blockIdx.x * G2_TBM;
    if (m0 >= mEnd) return;
    const int h0 = blockIdx.y * G2_TBN;

    __shared__ __align__(16) uint32_t dsm[2 * G2_AW + 2 * G2_BW];   // 40 KB

    const int t = threadIdx.x;
    const int w = t >> 5, l = t & 31;
    const int wm = w & 3, wn = w >> 2;      // warp tile 32x64
    const int lr = l >> 2, lc = l & 3;
    const uint32_t smb = su32(dsm);
    const int lmRow = l & 15;
    const int lmChk = (l >> 4) * 4;

    const float* w2e = w2 + (size_t)e * dI * dH + h0;

    // A staging: 128 rows x 32k halfs -> 2 uint4 per thread
    int aOffW[2];
    const __half* aSrc[2];
    #pragma unroll
    for (int p = 0; p < 2; ++p) {
        int id = t + p * NTH;
        int row = id >> 2, qc = id & 3;
        aOffW[p] = row * AST + qc * 4;
        int grow = (m0 + row < mEnd) ? (m0 + row) : m0;
        aSrc[p] = g_h + (size_t)grow * dI + qc * 8;
    }
    // B staging: 128 n x 32 k: n = t&127, kb = (t>>7)*16 -> 16 floats, 8 words
    const int bN = t & 127, bKb = (t >> 7) * 16;
    const int bOffW = bN * AST + (bKb >> 1);
    const float* bSrc = w2e + (size_t)bKb * dH + bN;

    uint4 uA[2];
    uint32_t uB[8];

    auto ldg_stage = [&](int kt) {
        const int k0 = kt * TBK;
        #pragma unroll
        for (int p = 0; p < 2; ++p)
            uA[p] = *(const uint4*)(aSrc[p] + k0);
        const float* pb = bSrc + (size_t)k0 * dH;
        #pragma unroll
        for (int jj = 0; jj < 8; ++jj)
            uB[jj] = packh2(pb[(size_t)(2 * jj) * dH], pb[(size_t)(2 * jj + 1) * dH]);
    };
    auto sts_stage = [&](int s) {
        #pragma unroll
        for (int p = 0; p < 2; ++p)
            *(uint4*)&dsm[s * G2_AW + aOffW[p]] = uA[p];
        *(uint4*)&dsm[2 * G2_AW + s * G2_BW + bOffW] =
            make_uint4(uB[0], uB[1], uB[2], uB[3]);
        *(uint4*)&dsm[2 * G2_AW + s * G2_BW + bOffW + 4] =
            make_uint4(uB[4], uB[5], uB[6], uB[7]);
    };

    float acc[2][8][4] = {};

    const int KT = dI / TBK;   // 128
    ldg_stage(0);
    sts_stage(0);
    __syncthreads();

    for (int kt = 0; kt < KT; ++kt) {
        const int s = kt & 1;
        if (kt + 1 < KT) ldg_stage(kt + 1);

        #pragma unroll
        for (int ks = 0; ks < 2; ++ks) {
            const int kw = ks * 8 + lmChk;
            uint32_t af[2][4];
            #pragma unroll
            for (int mi = 0; mi < 2; ++mi) {
                int r = wm * 32 + mi * 16 + lmRow;
                ldmx4(af[mi], smb + 4u * (uint32_t)(s * G2_AW + r * AST + kw));
            }
            uint32_t bf[8][2];
            #pragma unroll
            for (int np = 0; np < 4; ++np) {
                int n = wn * 64 + np * 16 + lmRow;
                uint32_t q[4];
                ldmx4(q, smb + 4u * (uint32_t)(2 * G2_AW + s * G2_BW + n * AST + kw));
                bf[np * 2][0] = q[0]; bf[np * 2 + 1][0] = q[1];
                bf[np * 2][1] = q[2]; bf[np * 2 + 1][1] = q[3];
            }
            #pragma unroll
            for (int ni = 0; ni < 8; ++ni)
                #pragma unroll
                for (int mi = 0; mi < 2; ++mi)
                    mma_f16(acc[mi][ni], af[mi], bf[ni]);
        }

        if (kt + 1 < KT) sts_stage(s ^ 1);
        __syncthreads();
    }

    // fused epilogue: out[token] += ew * acc (exactly 2 adds per element)
    #pragma unroll
    for (int mi = 0; mi < 2; ++mi) {
        int r0 = m0 + wm * 32 + mi * 16 + lr;
        int r1 = r0 + 8;
        int tk0 = -1, tk1 = -1;
        float wg0 = 0.0f, wg1 = 0.0f;
        if (r0 < mEnd) { int p = g_pairs[r0]; wg0 = ew[p]; tk0 = p / dK; }
        if (r1 < mEnd) { int p = g_pairs[r1]; wg1 = ew[p]; tk1 = p / dK; }
        #pragma unroll
        for (int ni = 0; ni < 8; ++ni) {
            int c = h0 + wn * 64 + ni * 8 + lc * 2;
            if (tk0 >= 0) {
                atomicAdd(&out[(size_t)tk0 * dH + c],     wg0 * acc[mi][ni][0]);
                atomicAdd(&out[(size_t)tk0 * dH + c + 1], wg0 * acc[mi][ni][1]);
            }
            if (tk1 >= 0) {
                atomicAdd(&out[(size_t)tk1 * dH + c],     wg1 * acc[mi][ni][2]);
                atomicAdd(&out[(size_t)tk1 * dH + c + 1], wg1 * acc[mi][ni][3]);
            }
        }
    }
}

extern "C" void kernel_launch(void* const* d_in, const int* in_sizes, int n_in,
                              void* d_out, int out_size) {
    const float* x   = (const float*)d_in[0];
    const int*   idx = (const int*)  d_in[1];
    const float* ew  = (const float*)d_in[2];
    const float* w1  = (const float*)d_in[3];
    const float* w2  = (const float*)d_in[4];
    const float* w3  = (const float*)d_in[5];
    float* out = (float*)d_out;

    const int smem1 = (2 * G1_AW + 4 * G1_BW) * 4;   // 61440 B
    cudaFuncSetAttribute(gemm1_mma, cudaFuncAttributeMaxDynamicSharedMemorySize, smem1);

    route_kernel<<<1, 256>>>(idx);
    zero_out_kernel<<<(dN * dH / 4 + 255) / 256, 256>>>(out);
    dim3 g1(dNK / G1_TBM, dI / G1_TBN, dE);   // 16 x 64 x 8
    gemm1_mma<<<g1, NTH, smem1>>>(x, w1, w3);
    dim3 g2(dNK / G2_TBM, dH / G2_TBN, dE);   // 32 x 8 x 8
    gemm2_mma<<<g2, NTH>>>(ew, w2, out);
}